// round 1
// baseline (speedup 1.0000x reference)
#include <cuda_runtime.h>

// Problem constants
#define BB   4
#define CC   128
#define HW   224
#define PHW  7
#define HH   32      // HW/PHW
#define MM   1024    // HH*HH
#define PP   49      // PHW*PHW
#define FS   132     // smem stride for flat[p][*] (16B-aligned, conflict-friendly)
#define GS   129     // smem stride for G[c][*]
#define ALPHA 0.5f

// d_out chunk offsets (elements), tuple order: out, Sc, cov, Ec_map
#define N_OUT 25690112ull           // 4*128*224*224
#define N_SCC 67108864ull           // 4*1024*128*128

__global__ __launch_bounds__(256, 2)
void bdca_kernel(const float* __restrict__ x, const float* __restrict__ beta,
                 float* __restrict__ out, float* __restrict__ Sc,
                 float* __restrict__ cov, float* __restrict__ ecmap)
{
    extern __shared__ float sm[];
    float* fl   = sm;                  // [PP][FS]  flat, layout fl[p*FS + c]
    float* G    = sm + PP * FS;        // [CC][GS]
    float* mu   = G + CC * GS;         // [CC]
    float* rmax = mu + CC;             // [CC]
    float* rsum = rmax + CC;           // [CC]  (stores 1/sum)
    float* pbuf = rsum + CC;           // [256] partials

    const int tid = threadIdx.x;
    const int bm  = blockIdx.x;
    const int b   = bm >> 10;
    const int m   = bm & 1023;
    const int hh  = m >> 5;
    const int ww  = m & 31;

    const size_t xoff = (size_t)b * CC * HW * HW + (size_t)(hh * PHW) * HW + (size_t)(ww * PHW);
    const float* xb = x + xoff;

    // ---- Stage flat[p][c] = x[b, c, hh*7+i, ww*7+j],  p = i*7+j ----
    for (int idx = tid; idx < CC * PP; idx += 256) {
        int c = idx / PP;
        int p = idx - c * PP;
        int i = p / PHW;
        int j = p - i * PHW;
        fl[p * FS + c] = xb[(size_t)c * (HW * HW) + i * HW + j];
    }
    __syncthreads();

    // ---- mean over P per channel (threads 0..127) ----
    if (tid < CC) {
        float s = 0.f;
        #pragma unroll
        for (int p = 0; p < PP; p++) s += fl[p * FS + tid];
        mu[tid] = s * (1.f / PP);
    }

    // ---- GEMM1: G = flat * flat^T, 8x8 register tiles ----
    const int ty = tid >> 4, tx = tid & 15;
    const int c0 = ty * 8, d0 = tx * 8;
    float acc[8][8];
    #pragma unroll
    for (int i = 0; i < 8; i++)
        #pragma unroll
        for (int j = 0; j < 8; j++) acc[i][j] = 0.f;

    for (int p = 0; p < PP; p++) {
        const float* row = fl + p * FS;
        float4 a0 = *(const float4*)(row + c0);
        float4 a1 = *(const float4*)(row + c0 + 4);
        float4 b0 = *(const float4*)(row + d0);
        float4 b1 = *(const float4*)(row + d0 + 4);
        float av[8] = {a0.x, a0.y, a0.z, a0.w, a1.x, a1.y, a1.z, a1.w};
        float bv[8] = {b0.x, b0.y, b0.z, b0.w, b1.x, b1.y, b1.z, b1.w};
        #pragma unroll
        for (int i = 0; i < 8; i++)
            #pragma unroll
            for (int j = 0; j < 8; j++)
                acc[i][j] = fmaf(av[i], bv[j], acc[i][j]);
    }
    #pragma unroll
    for (int i = 0; i < 8; i++)
        #pragma unroll
        for (int j = 0; j < 8; j++)
            G[(c0 + i) * GS + d0 + j] = acc[i][j];
    __syncthreads();

    // ---- Row max / sum(exp) : 2 threads per row ----
    {
        const int r = tid >> 1, hf = tid & 1;
        const float* Gr = G + r * GS + hf * 64;
        float mx = -3.4e38f;
        #pragma unroll 8
        for (int d = 0; d < 64; d++) mx = fmaxf(mx, Gr[d]);
        pbuf[tid] = mx;
        __syncthreads();
        if (hf == 0) rmax[r] = fmaxf(pbuf[tid], pbuf[tid + 1]);
        __syncthreads();
        float rm = rmax[r];
        float s = 0.f;
        #pragma unroll 8
        for (int d = 0; d < 64; d++) s += __expf(Gr[d] - rm);
        pbuf[tid] = s;
        __syncthreads();
        if (hf == 0) rsum[r] = 1.f / (pbuf[tid] + pbuf[tid + 1]);
        __syncthreads();
    }

    // ---- Epilogue A: write Sc & cov (coalesced), build L = Sc + alpha*cov in G ----
    {
        const size_t obase = (size_t)bm * (CC * CC);
        for (int idx = tid; idx < CC * CC; idx += 256) {
            int c = idx >> 7, d = idx & 127;
            float g  = G[c * GS + d];
            float sc = __expf(g - rmax[c]) * rsum[c];
            float cv = g * (1.f / PP) - mu[c] * mu[d];
            Sc[obase + idx]  = sc;
            cov[obase + idx] = cv;
            G[c * GS + d] = fmaf(ALPHA, cv, sc);
        }
    }
    __syncthreads();

    // ---- GEMM2: Ec = L * flat  (output 128 x 49), 8x4 register tiles ----
    float acc2[8][4];
    #pragma unroll
    for (int i = 0; i < 8; i++)
        #pragma unroll
        for (int j = 0; j < 4; j++) acc2[i][j] = 0.f;

    int pidx[4], pld[4];
    #pragma unroll
    for (int j = 0; j < 4; j++) {
        pidx[j] = tx + 16 * j;
        pld[j]  = (pidx[j] < PP) ? pidx[j] : 0;   // safe load addr; store is masked
    }

    for (int d = 0; d < CC; d++) {
        float bv[4];
        #pragma unroll
        for (int j = 0; j < 4; j++) bv[j] = fl[pld[j] * FS + d];
        #pragma unroll
        for (int i = 0; i < 8; i++) {
            float a = G[(c0 + i) * GS + d];
            #pragma unroll
            for (int j = 0; j < 4; j++)
                acc2[i][j] = fmaf(a, bv[j], acc2[i][j]);
        }
    }
    __syncthreads();   // all GEMM2 reads of G done -> safe to overwrite with Ec

    // Stage Ec into G region: Ec_s[c*GS + p]
    #pragma unroll
    for (int i = 0; i < 8; i++)
        #pragma unroll
        for (int j = 0; j < 4; j++)
            if (pidx[j] < PP) G[(c0 + i) * GS + pidx[j]] = acc2[i][j];
    __syncthreads();

    // ---- Epilogue B: fold + out = x * (beta*Ec + x) ----
    {
        const float beta0 = beta[0];
        for (int idx = tid; idx < CC * PP; idx += 256) {
            int c = idx / PP;
            int p = idx - c * PP;
            int i = p / PHW;
            int j = p - i * PHW;
            float xv = fl[p * FS + c];
            float ec = G[c * GS + p];
            size_t g = xoff + (size_t)c * (HW * HW) + i * HW + j;
            ecmap[g] = ec;
            out[g]   = xv * fmaf(beta0, ec, xv);
        }
    }
}

extern "C" void kernel_launch(void* const* d_in, const int* in_sizes, int n_in,
                              void* d_out, int out_size)
{
    const float* x    = (const float*)d_in[0];
    const float* beta = (const float*)d_in[1];

    float* out   = (float*)d_out;
    float* Sc    = out + N_OUT;
    float* cov   = Sc + N_SCC;
    float* ecmap = cov + N_SCC;

    const int smem_bytes = (PP * FS + CC * GS + 3 * CC + 256) * (int)sizeof(float);
    cudaFuncSetAttribute(bdca_kernel, cudaFuncAttributeMaxDynamicSharedMemorySize, smem_bytes);
    bdca_kernel<<<BB * MM, 256, smem_bytes>>>(x, beta, out, Sc, cov, ecmap);
}

// round 2
// speedup vs baseline: 1.1695x; 1.1695x over previous
#include <cuda_runtime.h>

// Problem constants
#define BB   4
#define CC   128
#define HW   224
#define PHW  7
#define MM   1024    // (HW/PHW)^2
#define PP   49
#define FS   132     // smem stride for flat[p][*] (16B aligned rows)
#define GS   132     // smem stride for G[c][*]   (16B aligned rows)
#define ALPHA 0.5f

#define N_OUT 25690112ull           // 4*128*224*224
#define N_SCC 67108864ull           // 4*1024*128*128

typedef unsigned long long ull;

#define FMA_F32X2(d, a, b, c) \
    asm("fma.rn.f32x2 %0, %1, %2, %3;" : "=l"(d) : "l"(a), "l"(b), "l"(c))
#define PACK_F32X2(out, lo, hi) \
    asm("mov.b64 %0, {%1, %2};" : "=l"(out) : "f"(lo), "f"(hi))
#define UNPACK_F32X2(lo, hi, in) \
    asm("mov.b64 {%0, %1}, %2;" : "=f"(lo), "=f"(hi) : "l"(in))

__global__ __launch_bounds__(256, 2)
void bdca_kernel(const float* __restrict__ x, const float* __restrict__ beta,
                 float* __restrict__ out, float* __restrict__ Sc,
                 float* __restrict__ cov, float* __restrict__ ecmap)
{
    extern __shared__ float sm[];
    float* fl   = sm;                  // [PP][FS]  fl[p*FS + c]
    float* G    = sm + PP * FS;        // [CC][GS]
    float* mu   = G + CC * GS;         // [CC]
    float* rmax = mu + CC;             // [CC]
    float* rsum = rmax + CC;           // [CC]  (1/sum)
    float* pbuf = rsum + CC;           // [256]

    const int tid = threadIdx.x;
    const int bm  = blockIdx.x;
    const int b   = bm >> 10;
    const int m   = bm & 1023;
    const int hh  = m >> 5;
    const int ww  = m & 31;

    const size_t xoff = (size_t)b * CC * HW * HW + (size_t)(hh * PHW) * HW + (size_t)(ww * PHW);
    const float* xb = x + xoff;

    // ---- Stage flat[p][c] ----
    for (int idx = tid; idx < CC * PP; idx += 256) {
        int c = idx / PP;
        int p = idx - c * PP;
        int i = p / PHW;
        int j = p - i * PHW;
        fl[p * FS + c] = xb[(size_t)c * (HW * HW) + i * HW + j];
    }
    __syncthreads();

    // ---- mean over P per channel ----
    if (tid < CC) {
        float s = 0.f;
        #pragma unroll
        for (int p = 0; p < PP; p++) s += fl[p * FS + tid];
        mu[tid] = s * (1.f / PP);
    }

    // ---- GEMM1: G = flat*flat^T, 8x8 tiles, f32x2 FMA (pair over d-columns) ----
    const int ty = tid >> 4, tx = tid & 15;
    const int c0 = ty * 8, d0 = tx * 8;

    ull accp[8][4];
    #pragma unroll
    for (int i = 0; i < 8; i++)
        #pragma unroll
        for (int j = 0; j < 4; j++) accp[i][j] = 0ull;

    for (int p = 0; p < PP; p++) {
        const float* row = fl + p * FS;
        float4 a0 = *(const float4*)(row + c0);
        float4 a1 = *(const float4*)(row + c0 + 4);
        float4 b0 = *(const float4*)(row + d0);
        float4 b1 = *(const float4*)(row + d0 + 4);
        float av[8] = {a0.x, a0.y, a0.z, a0.w, a1.x, a1.y, a1.z, a1.w};
        ull bvp[4];
        PACK_F32X2(bvp[0], b0.x, b0.y);
        PACK_F32X2(bvp[1], b0.z, b0.w);
        PACK_F32X2(bvp[2], b1.x, b1.y);
        PACK_F32X2(bvp[3], b1.z, b1.w);
        #pragma unroll
        for (int i = 0; i < 8; i++) {
            ull ap;
            PACK_F32X2(ap, av[i], av[i]);
            #pragma unroll
            for (int j = 0; j < 4; j++)
                FMA_F32X2(accp[i][j], ap, bvp[j], accp[i][j]);
        }
    }
    #pragma unroll
    for (int i = 0; i < 8; i++)
        #pragma unroll
        for (int j = 0; j < 4; j++) {
            float lo, hi;
            UNPACK_F32X2(lo, hi, accp[i][j]);
            float2 v = make_float2(lo, hi);
            *(float2*)(G + (c0 + i) * GS + d0 + 2 * j) = v;
        }
    __syncthreads();

    // ---- Row max / sum(exp): 2 threads per row ----
    {
        const int r = tid >> 1, hf = tid & 1;
        const float* Gr = G + r * GS + hf * 64;
        float mx = -3.4e38f;
        #pragma unroll 8
        for (int d = 0; d < 64; d++) mx = fmaxf(mx, Gr[d]);
        pbuf[tid] = mx;
        __syncthreads();
        if (hf == 0) rmax[r] = fmaxf(pbuf[tid], pbuf[tid + 1]);
        __syncthreads();
        float rm = rmax[r];
        float s = 0.f;
        #pragma unroll 8
        for (int d = 0; d < 64; d++) s += __expf(Gr[d] - rm);
        pbuf[tid] = s;
        __syncthreads();
        if (hf == 0) rsum[r] = 1.f / (pbuf[tid] + pbuf[tid + 1]);
        __syncthreads();
    }

    // ---- Epilogue A (vectorized): write Sc & cov, build L in G ----
    {
        const size_t obase = (size_t)bm * (CC * CC);
        for (int idx4 = tid; idx4 < (CC * CC) / 4; idx4 += 256) {
            int c  = idx4 >> 5;
            int d4 = (idx4 & 31) << 2;
            float4 g   = *(float4*)(G + c * GS + d4);
            float4 muv = *(float4*)(mu + d4);
            float rm = rmax[c], rs = rsum[c], mc = mu[c];
            float4 sc, cv, L;
            sc.x = __expf(g.x - rm) * rs;
            sc.y = __expf(g.y - rm) * rs;
            sc.z = __expf(g.z - rm) * rs;
            sc.w = __expf(g.w - rm) * rs;
            cv.x = g.x * (1.f / PP) - mc * muv.x;
            cv.y = g.y * (1.f / PP) - mc * muv.y;
            cv.z = g.z * (1.f / PP) - mc * muv.z;
            cv.w = g.w * (1.f / PP) - mc * muv.w;
            L.x = fmaf(ALPHA, cv.x, sc.x);
            L.y = fmaf(ALPHA, cv.y, sc.y);
            L.z = fmaf(ALPHA, cv.z, sc.z);
            L.w = fmaf(ALPHA, cv.w, sc.w);
            *(float4*)(Sc  + obase + (size_t)idx4 * 4) = sc;
            *(float4*)(cov + obase + (size_t)idx4 * 4) = cv;
            *(float4*)(G + c * GS + d4) = L;
        }
    }
    __syncthreads();

    // ---- GEMM2: Ec = L*flat (128 x 49), d-contiguous float4 loads,
    //      f32x2 accumulators over the reduction (horizontal add at end) ----
    ull acc2p[8][4];
    #pragma unroll
    for (int i = 0; i < 8; i++)
        #pragma unroll
        for (int j = 0; j < 4; j++) acc2p[i][j] = 0ull;

    int pidx[4], pld[4];
    #pragma unroll
    for (int j = 0; j < 4; j++) {
        pidx[j] = tx + 16 * j;
        pld[j]  = (pidx[j] < PP) ? pidx[j] : 0;
    }

    for (int d = 0; d < CC; d += 4) {
        ull fb01[4], fb23[4];
        #pragma unroll
        for (int j = 0; j < 4; j++) {
            float4 fb = *(const float4*)(fl + pld[j] * FS + d);
            PACK_F32X2(fb01[j], fb.x, fb.y);
            PACK_F32X2(fb23[j], fb.z, fb.w);
        }
        #pragma unroll
        for (int i = 0; i < 8; i++) {
            float4 ga = *(const float4*)(G + (c0 + i) * GS + d);
            ull ga01, ga23;
            PACK_F32X2(ga01, ga.x, ga.y);
            PACK_F32X2(ga23, ga.z, ga.w);
            #pragma unroll
            for (int j = 0; j < 4; j++) {
                FMA_F32X2(acc2p[i][j], ga01, fb01[j], acc2p[i][j]);
                FMA_F32X2(acc2p[i][j], ga23, fb23[j], acc2p[i][j]);
            }
        }
    }
    __syncthreads();   // all GEMM2 reads of G done

    // Stage Ec into G region: Ec_s[c*GS + p]
    #pragma unroll
    for (int i = 0; i < 8; i++)
        #pragma unroll
        for (int j = 0; j < 4; j++)
            if (pidx[j] < PP) {
                float lo, hi;
                UNPACK_F32X2(lo, hi, acc2p[i][j]);
                G[(c0 + i) * GS + pidx[j]] = lo + hi;
            }
    __syncthreads();

    // ---- Epilogue B: fold + out = x * (beta*Ec + x) ----
    {
        const float beta0 = beta[0];
        for (int idx = tid; idx < CC * PP; idx += 256) {
            int c = idx / PP;
            int p = idx - c * PP;
            int i = p / PHW;
            int j = p - i * PHW;
            float xv = fl[p * FS + c];
            float ec = G[c * GS + p];
            size_t g = xoff + (size_t)c * (HW * HW) + i * HW + j;
            ecmap[g] = ec;
            out[g]   = xv * fmaf(beta0, ec, xv);
        }
    }
}

extern "C" void kernel_launch(void* const* d_in, const int* in_sizes, int n_in,
                              void* d_out, int out_size)
{
    const float* x    = (const float*)d_in[0];
    const float* beta = (const float*)d_in[1];

    float* out   = (float*)d_out;
    float* Sc    = out + N_OUT;
    float* cov   = Sc + N_SCC;
    float* ecmap = cov + N_SCC;

    const int smem_bytes = (PP * FS + CC * GS + 3 * CC + 256) * (int)sizeof(float);
    cudaFuncSetAttribute(bdca_kernel, cudaFuncAttributeMaxDynamicSharedMemorySize, smem_bytes);
    bdca_kernel<<<BB * MM, 256, smem_bytes>>>(x, beta, out, Sc, cov, ecmap);
}